// round 2
// baseline (speedup 1.0000x reference)
#include <cuda_runtime.h>
#include <cuda_bf16.h>
#include <cstdint>

#define N_ROIS 250000
#define G      128
#define NTOT   (N_ROIS + G)      // 250128
#define NBINS  4100
#define CANDCAP 2048
#define FG_ROIS 128
#define BG_ROIS 128

// ---------------- scratch (device globals; no allocation) ----------------
__device__ int           g_gtassign[NTOT];
__device__ unsigned      g_kf[NTOT];
__device__ unsigned      g_kb[NTOT];
__device__ unsigned      g_hist[2][NBINS];
__device__ unsigned      g_cnt[2];
__device__ int           g_thr[2];
__device__ unsigned long long g_cand[2][CANDCAP];
__device__ unsigned      g_keep[256];

// ---------------- threefry2x32 with key (0, 42) ----------------
__device__ __forceinline__ uint2 threefry42(unsigned x0, unsigned x1) {
    const unsigned ks0 = 0u;
    const unsigned ks1 = 42u;
    const unsigned ks2 = 0x1BD11BDAu ^ ks0 ^ ks1;
#define TF_ROUND(r) { x0 += x1; x1 = (x1 << (r)) | (x1 >> (32 - (r))); x1 ^= x0; }
    x0 += ks0; x1 += ks1;
    TF_ROUND(13) TF_ROUND(15) TF_ROUND(26) TF_ROUND(6)
    x0 += ks1; x1 += ks2 + 1u;
    TF_ROUND(17) TF_ROUND(29) TF_ROUND(16) TF_ROUND(24)
    x0 += ks2; x1 += ks0 + 2u;
    TF_ROUND(13) TF_ROUND(15) TF_ROUND(26) TF_ROUND(6)
    x0 += ks0; x1 += ks1 + 3u;
    TF_ROUND(17) TF_ROUND(29) TF_ROUND(16) TF_ROUND(24)
    x0 += ks1; x1 += ks2 + 4u;
    TF_ROUND(13) TF_ROUND(15) TF_ROUND(26) TF_ROUND(6)
    x0 += ks2; x1 += ks0 + 5u;
#undef TF_ROUND
    return make_uint2(x0, x1);
}

// partitionable threefry random_bits (jax_threefry_partitionable=True):
// element i uses counter (hi32(i), lo32(i)) = (0, i); 32-bit draw = x0out ^ x1out
__device__ __forceinline__ unsigned jax_bits_partitionable(unsigned i) {
    uint2 y = threefry42(0u, i);
    return y.x ^ y.y;
}

// ---------------- K0: zero scratch ----------------
__global__ void k_zero() {
    int i = blockIdx.x * blockDim.x + threadIdx.x;
    int tot = 2 * NBINS;
    if (i < tot) ((unsigned*)g_hist)[i] = 0u;
    if (i < 2) g_cnt[i] = 0u;
}

// ---------------- K1: IoU max/argmax + threefry keys + histogram ----------------
__global__ void __launch_bounds__(256) k_iou(const float* __restrict__ all_rois,
                                             const float* __restrict__ gtb) {
    __shared__ float gx1[G], gy1[G], gx2[G], gy2[G], ga[G];
    int tid = threadIdx.x;
    if (tid < G) {
        float x1 = gtb[tid * 4 + 0], y1 = gtb[tid * 4 + 1];
        float x2 = gtb[tid * 4 + 2], y2 = gtb[tid * 4 + 3];
        gx1[tid] = x1; gy1[tid] = y1; gx2[tid] = x2; gy2[tid] = y2;
        ga[tid] = __fmul_rn(x2 - x1 + 1.0f, y2 - y1 + 1.0f);
    }
    __syncthreads();

    int i = blockIdx.x * blockDim.x + tid;
    if (i >= NTOT) return;

    float ax1, ay1, ax2, ay2;
    if (i < N_ROIS) {
        const float* p = all_rois + (size_t)i * 5;
        ax1 = p[1]; ay1 = p[2]; ax2 = p[3]; ay2 = p[4];
    } else {
        const float* p = gtb + (size_t)(i - N_ROIS) * 4;
        ax1 = p[0]; ay1 = p[1]; ax2 = p[2]; ay2 = p[3];
    }
    float aa = __fmul_rn(ax2 - ax1 + 1.0f, ay2 - ay1 + 1.0f);

    float bnum = 0.0f, bden = 1.0f;
    int bj = 0;
#pragma unroll 4
    for (int j = 0; j < G; j++) {
        float xx1 = fmaxf(ax1, gx1[j]);
        float yy1 = fmaxf(ay1, gy1[j]);
        float xx2 = fminf(ax2, gx2[j]);
        float yy2 = fminf(ay2, gy2[j]);
        float iw = fmaxf(xx2 - xx1 + 1.0f, 0.0f);
        float ih = fmaxf(yy2 - yy1 + 1.0f, 0.0f);
        float inter = __fmul_rn(iw, ih);
        float den = (aa + ga[j]) - inter;
        // inter/den > bnum/bden  <=>  inter*bden > bnum*den  (den,bden > 0)
        if (__fmul_rn(inter, bden) > __fmul_rn(bnum, den)) {
            bnum = inter; bden = den; bj = j;
        }
    }
    g_gtassign[i] = bj;
    float mov = __fdiv_rn(bnum, bden);
    bool fg = (mov >= 0.5f);
    bool bg = (mov < 0.5f) && (mov >= 0.1f);

    unsigned bits = jax_bits_partitionable((unsigned)i);
    unsigned m = (bits >> 9) + 1u;   // 1..2^23; monotonic in u; 0 = masked-out

    unsigned kf = fg ? m : 0u;
    unsigned kb = bg ? m : 0u;
    g_kf[i] = kf;
    g_kb[i] = kb;
    if (fg) atomicAdd(&g_hist[0][m >> 11], 1u);
    if (bg) atomicAdd(&g_hist[1][m >> 11], 1u);
}

// ---------------- K2: find radix-select thresholds ----------------
__global__ void k_thresh() {
    int s = threadIdx.x;
    if (s < 2) {
        unsigned acc = 0;
        int B = 0;
        for (int b = NBINS - 1; b >= 0; b--) {
            acc += g_hist[s][b];
            if (acc >= 128u) { B = b; break; }
        }
        g_thr[s] = B;
    }
}

// ---------------- K3: compact candidates above threshold ----------------
__global__ void __launch_bounds__(256) k_compact() {
    int i = blockIdx.x * blockDim.x + threadIdx.x;
    if (i >= NTOT) return;
    unsigned kf = g_kf[i];
    if (kf != 0u && (int)(kf >> 11) >= g_thr[0]) {
        unsigned p = atomicAdd(&g_cnt[0], 1u);
        if (p < CANDCAP)
            g_cand[0][p] = ((unsigned long long)kf << 32) | (unsigned)(0xFFFFFFFFu - (unsigned)i);
    }
    unsigned kb = g_kb[i];
    if (kb != 0u && (int)(kb >> 11) >= g_thr[1]) {
        unsigned p = atomicAdd(&g_cnt[1], 1u);
        if (p < CANDCAP)
            g_cand[1][p] = ((unsigned long long)kb << 32) | (unsigned)(0xFFFFFFFFu - (unsigned)i);
    }
}

// ---------------- K4: bitonic sort candidates, emit keep indices ----------------
__global__ void __launch_bounds__(256) k_sort() {
    __shared__ unsigned long long s[CANDCAP];
    int sel = blockIdx.x;
    unsigned n = g_cnt[sel];
    if (n > CANDCAP) n = CANDCAP;
    for (int t = threadIdx.x; t < CANDCAP; t += 256)
        s[t] = (t < (int)n) ? g_cand[sel][t] : 0ull;
    __syncthreads();

    for (unsigned k = 2; k <= CANDCAP; k <<= 1) {
        for (unsigned j = k >> 1; j > 0; j >>= 1) {
            for (int t = threadIdx.x; t < CANDCAP; t += 256) {
                unsigned ixj = t ^ j;
                if (ixj > (unsigned)t) {
                    bool up = ((t & k) == 0);
                    unsigned long long a = s[t], b = s[ixj];
                    if (up ? (a > b) : (a < b)) { s[t] = b; s[ixj] = a; }
                }
            }
            __syncthreads();
        }
    }
    // ascending sort -> top-128 from the end, descending (matches jax top_k order;
    // ties break to lower index via ~index in low bits)
    for (int r = threadIdx.x; r < 128; r += 256) {
        unsigned long long kv = s[CANDCAP - 1 - r];
        unsigned idx = 0xFFFFFFFFu - (unsigned)(kv & 0xFFFFFFFFu);
        if (idx >= NTOT) idx = 0;
        g_keep[sel * 128 + r] = idx;
    }
}

// ---------------- K5: gather rois, labels, bbox targets ----------------
__global__ void __launch_bounds__(256) k_out(const float* __restrict__ all_rois,
                                             const float* __restrict__ gtb,
                                             const int* __restrict__ gtl,
                                             float* __restrict__ out) {
    int r = threadIdx.x;  // 0..255
    unsigned idx = g_keep[r];

    float c0, x1, y1, x2, y2;
    if (idx < N_ROIS) {
        const float* p = all_rois + (size_t)idx * 5;
        c0 = p[0]; x1 = p[1]; y1 = p[2]; x2 = p[3]; y2 = p[4];
    } else {
        const float* p = gtb + (size_t)(idx - N_ROIS) * 4;
        c0 = 0.0f; x1 = p[0]; y1 = p[1]; x2 = p[2]; y2 = p[3];
    }
    int ga = g_gtassign[idx];

    int label = 0;
    if (r < FG_ROIS && g_kf[idx] != 0u) label = gtl[ga];

    // rois [256,5] at offset 0
    out[r * 5 + 0] = c0;
    out[r * 5 + 1] = x1;
    out[r * 5 + 2] = y1;
    out[r * 5 + 3] = x2;
    out[r * 5 + 4] = y2;
    // labels [256] at offset 1280
    out[1280 + r] = (float)label;
    // bbox_targets [256,84] at offset 1536
    float* bt = out + 1536 + (size_t)r * 84;
#pragma unroll
    for (int c = 0; c < 84; c++) bt[c] = 0.0f;

    if (label > 0) {
        const float* g = gtb + (size_t)ga * 4;
        float ew = x2 - x1 + 1.0f, eh = y2 - y1 + 1.0f;
        float ecx = x1 + 0.5f * ew, ecy = y1 + 0.5f * eh;
        float gw = g[2] - g[0] + 1.0f, gh = g[3] - g[1] + 1.0f;
        float gcx = g[0] + 0.5f * gw, gcy = g[1] + 0.5f * gh;
        bt[label * 4 + 0] = (gcx - ecx) / ew;
        bt[label * 4 + 1] = (gcy - ecy) / eh;
        bt[label * 4 + 2] = logf(gw / ew);
        bt[label * 4 + 3] = logf(gh / eh);
    }
}

// ---------------- launch ----------------
extern "C" void kernel_launch(void* const* d_in, const int* in_sizes, int n_in,
                              void* d_out, int out_size) {
    // identify inputs by element count (robust to ordering)
    const float* all_rois = nullptr;  // 1,250,000 elems
    const float* gtb      = nullptr;  // 512 elems
    const int*   gtl      = nullptr;  // 128 elems
    for (int k = 0; k < n_in; k++) {
        if (in_sizes[k] == N_ROIS * 5) all_rois = (const float*)d_in[k];
        else if (in_sizes[k] == G * 4) gtb = (const float*)d_in[k];
        else if (in_sizes[k] == G)     gtl = (const int*)d_in[k];
    }
    float* out = (float*)d_out;

    k_zero<<<(2 * NBINS + 511) / 512, 512>>>();
    k_iou<<<(NTOT + 255) / 256, 256>>>(all_rois, gtb);
    k_thresh<<<1, 32>>>();
    k_compact<<<(NTOT + 255) / 256, 256>>>();
    k_sort<<<2, 256>>>();
    k_out<<<1, 256>>>(all_rois, gtb, gtl, out);
}

// round 3
// speedup vs baseline: 1.4010x; 1.4010x over previous
#include <cuda_runtime.h>
#include <cuda_bf16.h>
#include <cstdint>

#define N_ROIS 250000
#define G      128
#define NTOT   (N_ROIS + G)      // 250128 (< 2^18)
#define NBK    4096
#define CAP    320
#define RPT    4                 // ROIs per thread in k_iou
#define TB     256               // threads per block in k_iou

// ---------------- scratch (device globals; no allocation) ----------------
__device__ unsigned            g_bcnt[2][NBK];
__device__ unsigned long long  g_bucket[2][NBK * CAP];   // ~21 MB
__device__ unsigned long long  g_keep64[256];

// ---------------- threefry2x32 with key (0, 42) ----------------
__device__ __forceinline__ uint2 threefry42(unsigned x0, unsigned x1) {
    const unsigned ks0 = 0u;
    const unsigned ks1 = 42u;
    const unsigned ks2 = 0x1BD11BDAu ^ ks0 ^ ks1;
#define TF_ROUND(r) { x0 += x1; x1 = (x1 << (r)) | (x1 >> (32 - (r))); x1 ^= x0; }
    x0 += ks0; x1 += ks1;
    TF_ROUND(13) TF_ROUND(15) TF_ROUND(26) TF_ROUND(6)
    x0 += ks1; x1 += ks2 + 1u;
    TF_ROUND(17) TF_ROUND(29) TF_ROUND(16) TF_ROUND(24)
    x0 += ks2; x1 += ks0 + 2u;
    TF_ROUND(13) TF_ROUND(15) TF_ROUND(26) TF_ROUND(6)
    x0 += ks0; x1 += ks1 + 3u;
    TF_ROUND(17) TF_ROUND(29) TF_ROUND(16) TF_ROUND(24)
    x0 += ks1; x1 += ks2 + 4u;
    TF_ROUND(13) TF_ROUND(15) TF_ROUND(26) TF_ROUND(6)
    x0 += ks2; x1 += ks0 + 5u;
#undef TF_ROUND
    return make_uint2(x0, x1);
}

// ---------------- K0: zero bucket counters ----------------
__global__ void k_zero() {
    int i = blockIdx.x * blockDim.x + threadIdx.x;
    if (i < 2 * NBK) ((unsigned*)g_bcnt)[i] = 0u;
}

// ---------------- K1: IoU max/argmax + key + bucket append ----------------
__global__ void __launch_bounds__(TB) k_iou(const float* __restrict__ rois,
                                            const float* __restrict__ gtb) {
    __shared__ float4 sb[G];   // x1,y1,x2,y2
    __shared__ float  sa[G];   // area_b
    int tid = threadIdx.x;
    if (tid < G) {
        float x1 = gtb[tid * 4 + 0], y1 = gtb[tid * 4 + 1];
        float x2 = gtb[tid * 4 + 2], y2 = gtb[tid * 4 + 3];
        sb[tid] = make_float4(x1, y1, x2, y2);
        sa[tid] = __fmul_rn(x2 - x1 + 1.0f, y2 - y1 + 1.0f);
    }
    __syncthreads();

    int base = blockIdx.x * (TB * RPT) + tid;

    float ax1[RPT], ay1[RPT], ax2[RPT], ay2[RPT], aa[RPT], bn[RPT], bs[RPT];
    int bj[RPT];
#pragma unroll
    for (int r = 0; r < RPT; r++) {
        int i = base + r * TB;
        int ii = (i < NTOT) ? i : 0;
        if (ii < N_ROIS) {
            const float* p = rois + (size_t)ii * 5;
            ax1[r] = p[1]; ay1[r] = p[2]; ax2[r] = p[3]; ay2[r] = p[4];
        } else {
            const float* p = gtb + (size_t)(ii - N_ROIS) * 4;
            ax1[r] = p[0]; ay1[r] = p[1]; ax2[r] = p[2]; ay2[r] = p[3];
        }
        aa[r] = __fmul_rn(ax2[r] - ax1[r] + 1.0f, ay2[r] - ay1[r] + 1.0f);
        bn[r] = 0.0f; bs[r] = 1.0f; bj[r] = 0;
    }

#pragma unroll 4
    for (int j = 0; j < G; j++) {
        float4 b = sb[j];
        float  ab = sa[j];
#pragma unroll
        for (int r = 0; r < RPT; r++) {
            float xx1 = fmaxf(ax1[r], b.x);
            float yy1 = fmaxf(ay1[r], b.y);
            float xx2 = fminf(ax2[r], b.z);
            float yy2 = fminf(ay2[r], b.w);
            float iw = fmaxf(xx2 - xx1 + 1.0f, 0.0f);
            float ih = fmaxf(yy2 - yy1 + 1.0f, 0.0f);
            float inter = __fmul_rn(iw, ih);
            float S = aa[r] + ab;   // area_a + area_b (same rounding as reference)
            // iou ordering: inter/(S-inter) ordering == inter/S ordering (exact, S>0)
            if (__fmul_rn(inter, bs[r]) > __fmul_rn(bn[r], S)) {
                bn[r] = inter; bs[r] = S; bj[r] = j;
            }
        }
    }

#pragma unroll
    for (int r = 0; r < RPT; r++) {
        int i = base + r * TB;
        if (i >= NTOT) continue;
        // max overlap with reference rounding: denom (area_a+area_b) - inter
        float mov = __fdiv_rn(bn[r], bs[r] - bn[r]);
        bool fg = (mov >= 0.5f);
        bool bg = (mov < 0.5f) && (mov >= 0.1f);
        if (fg || bg) {
            uint2 y = threefry42(0u, (unsigned)i);
            unsigned m = ((y.x ^ y.y) >> 9) + 1u;   // 1 .. 2^23, monotone in u
            unsigned long long rec =
                ((unsigned long long)m << 25) |
                ((unsigned long long)(0x3FFFFu - (unsigned)i) << 7) |
                (unsigned long long)(unsigned)bj[r];
            int sel = fg ? 0 : 1;
            unsigned bb = (m - 1u) >> 11;                 // 0..4095
            unsigned p = atomicAdd(&g_bcnt[sel][bb], 1u);
            if (p < CAP) g_bucket[sel][bb * CAP + p] = rec;
        }
    }
}

// ---------------- K2: radix select + bitonic sort top-128 per selector ----------------
__global__ void __launch_bounds__(512) k_select() {
    __shared__ unsigned           schunk[512];
    __shared__ unsigned long long skey[512];
    __shared__ int                sB;
    int sel = blockIdx.x;
    int t = threadIdx.x;

    unsigned loc[8];
    unsigned csum = 0;
#pragma unroll
    for (int k = 0; k < 8; k++) { loc[k] = g_bcnt[sel][t * 8 + k]; csum += loc[k]; }
    schunk[t] = csum;
    if (t == 0) sB = 0;
    __syncthreads();

    // suffix scan (inclusive from top) over 512 chunk sums
    for (int off = 1; off < 512; off <<= 1) {
        unsigned v = schunk[t];
        unsigned add = (t + off < 512) ? schunk[t + off] : 0u;
        __syncthreads();
        schunk[t] = v + add;
        __syncthreads();
    }
    unsigned ex = schunk[t] - csum;   // sum over chunks strictly above mine

    // per-bin inclusive-from-top cumulative C, local suffix within chunk
    unsigned Carr[8];
    {
        unsigned suf = 0;
#pragma unroll
        for (int k = 7; k >= 0; k--) { suf += loc[k]; Carr[k] = ex + suf; }
    }
#pragma unroll
    for (int k = 0; k < 8; k++)
        if (Carr[k] >= 128u) atomicMax(&sB, t * 8 + k);
    skey[t] = 0ull;
    __syncthreads();
    int B = sB;   // highest bin whose inclusive-from-top count reaches 128

    // gather entries from bins >= B into compact shared array (<= ~450 entries)
#pragma unroll
    for (int k = 0; k < 8; k++) {
        int bin = t * 8 + k;
        if (bin >= B && loc[k] > 0) {
            unsigned cnt = loc[k] < CAP ? loc[k] : CAP;
            unsigned off = Carr[k] - loc[k];   // entries in bins above this one
            for (unsigned e = 0; e < cnt; e++) {
                unsigned pos = off + e;
                if (pos < 512) skey[pos] = g_bucket[sel][bin * CAP + e];
            }
        }
    }
    __syncthreads();

    // bitonic sort 512 u64 ascending (1 element per thread)
    for (unsigned k = 2; k <= 512; k <<= 1) {
        for (unsigned j = k >> 1; j > 0; j >>= 1) {
            unsigned ixj = (unsigned)t ^ j;
            if (ixj > (unsigned)t) {
                bool up = ((t & k) == 0);
                unsigned long long a = skey[t], b = skey[ixj];
                if (up ? (a > b) : (a < b)) { skey[t] = b; skey[ixj] = a; }
            }
            __syncthreads();
        }
    }
    // top-128 descending by (key, then smaller original index first)
    if (t < 128) g_keep64[sel * 128 + t] = skey[511 - t];
}

// ---------------- K3: gather rois, labels, bbox targets ----------------
__global__ void __launch_bounds__(256) k_out(const float* __restrict__ rois,
                                             const float* __restrict__ gtb,
                                             const int* __restrict__ gtl,
                                             float* __restrict__ out) {
    int r = threadIdx.x;  // 0..255
    unsigned long long rec = g_keep64[r];
    unsigned idx = 0x3FFFFu - (unsigned)((rec >> 7) & 0x3FFFFu);
    int ga = (int)(rec & 0x7Fu);
    if (idx >= NTOT) { idx = 0; ga = 0; }

    float c0, x1, y1, x2, y2;
    if (idx < N_ROIS) {
        const float* p = rois + (size_t)idx * 5;
        c0 = p[0]; x1 = p[1]; y1 = p[2]; x2 = p[3]; y2 = p[4];
    } else {
        const float* p = gtb + (size_t)(idx - N_ROIS) * 4;
        c0 = 0.0f; x1 = p[0]; y1 = p[1]; x2 = p[2]; y2 = p[3];
    }

    // fg half: valid_fg is always true (>=128 fg guaranteed by gt self-match)
    int label = (r < 128) ? gtl[ga] : 0;

    // rois [256,5] at offset 0
    out[r * 5 + 0] = c0;
    out[r * 5 + 1] = x1;
    out[r * 5 + 2] = y1;
    out[r * 5 + 3] = x2;
    out[r * 5 + 4] = y2;
    // labels [256] at offset 1280
    out[1280 + r] = (float)label;
    // bbox_targets [256,84] at offset 1536
    float* bt = out + 1536 + (size_t)r * 84;
#pragma unroll
    for (int c = 0; c < 84; c++) bt[c] = 0.0f;

    if (label > 0) {
        const float* g = gtb + (size_t)ga * 4;
        float ew = x2 - x1 + 1.0f, eh = y2 - y1 + 1.0f;
        float ecx = x1 + 0.5f * ew, ecy = y1 + 0.5f * eh;
        float gw = g[2] - g[0] + 1.0f, gh = g[3] - g[1] + 1.0f;
        float gcx = g[0] + 0.5f * gw, gcy = g[1] + 0.5f * gh;
        bt[label * 4 + 0] = (gcx - ecx) / ew;
        bt[label * 4 + 1] = (gcy - ecy) / eh;
        bt[label * 4 + 2] = logf(gw / ew);
        bt[label * 4 + 3] = logf(gh / eh);
    }
}

// ---------------- launch ----------------
extern "C" void kernel_launch(void* const* d_in, const int* in_sizes, int n_in,
                              void* d_out, int out_size) {
    const float* all_rois = nullptr;  // 1,250,000 elems
    const float* gtb      = nullptr;  // 512 elems
    const int*   gtl      = nullptr;  // 128 elems
    for (int k = 0; k < n_in; k++) {
        if (in_sizes[k] == N_ROIS * 5) all_rois = (const float*)d_in[k];
        else if (in_sizes[k] == G * 4) gtb = (const float*)d_in[k];
        else if (in_sizes[k] == G)     gtl = (const int*)d_in[k];
    }
    float* out = (float*)d_out;

    k_zero<<<(2 * NBK + 511) / 512, 512>>>();
    k_iou<<<(NTOT + TB * RPT - 1) / (TB * RPT), TB>>>(all_rois, gtb);
    k_select<<<2, 512>>>();
    k_out<<<1, 256>>>(all_rois, gtb, gtl, out);
}

// round 5
// speedup vs baseline: 1.6776x; 1.1974x over previous
#include <cuda_runtime.h>
#include <cuda_bf16.h>
#include <cstdint>

#define N_ROIS 250000
#define G      128
#define NTOT   (N_ROIS + G)      // 250128 (< 2^18)
#define NBK    4096
#define CAP    320
#define RPT    4                 // ROIs per thread in k_iou
#define TB     256               // threads per block in k_iou

#define BBOX_ELEMS (256 * 84)    // 21504
#define CNT_WORDS  (2 * NBK)     // 8192

// ---------------- scratch (device globals; no allocation) ----------------
__device__ unsigned            g_bcnt[2][NBK];
__device__ unsigned long long  g_bucket[2][NBK * CAP];   // ~21 MB
__device__ unsigned long long  g_keep64[256];
__device__ int                 g_label[256];
__device__ float               g_tgt[256][4];

// ---------------- threefry2x32 with key (0, 42) ----------------
__device__ __forceinline__ uint2 threefry42(unsigned x0, unsigned x1) {
    const unsigned ks0 = 0u;
    const unsigned ks1 = 42u;
    const unsigned ks2 = 0x1BD11BDAu ^ ks0 ^ ks1;
#define TF_ROUND(r) { x0 += x1; x1 = (x1 << (r)) | (x1 >> (32 - (r))); x1 ^= x0; }
    x0 += ks0; x1 += ks1;
    TF_ROUND(13) TF_ROUND(15) TF_ROUND(26) TF_ROUND(6)
    x0 += ks1; x1 += ks2 + 1u;
    TF_ROUND(17) TF_ROUND(29) TF_ROUND(16) TF_ROUND(24)
    x0 += ks2; x1 += ks0 + 2u;
    TF_ROUND(13) TF_ROUND(15) TF_ROUND(26) TF_ROUND(6)
    x0 += ks0; x1 += ks1 + 3u;
    TF_ROUND(17) TF_ROUND(29) TF_ROUND(16) TF_ROUND(24)
    x0 += ks1; x1 += ks2 + 4u;
    TF_ROUND(13) TF_ROUND(15) TF_ROUND(26) TF_ROUND(6)
    x0 += ks2; x1 += ks0 + 5u;
#undef TF_ROUND
    return make_uint2(x0, x1);
}

// ---------------- K1: IoU max/argmax + key + bucket append ----------------
// NOTE: g_bcnt is zeroed at the END of the previous launch (k_fill tail),
// and __device__ globals are zero-initialized for the very first call.
__global__ void __launch_bounds__(TB) k_iou(const float* __restrict__ rois,
                                            const float* __restrict__ gtb) {
    __shared__ float4 sb[G];   // x1,y1,x2,y2
    __shared__ float  sa[G];   // area_b
    int tid = threadIdx.x;
    if (tid < G) {
        float x1 = gtb[tid * 4 + 0], y1 = gtb[tid * 4 + 1];
        float x2 = gtb[tid * 4 + 2], y2 = gtb[tid * 4 + 3];
        sb[tid] = make_float4(x1, y1, x2, y2);
        sa[tid] = __fmul_rn(x2 - x1 + 1.0f, y2 - y1 + 1.0f);
    }
    __syncthreads();

    int base = blockIdx.x * (TB * RPT) + tid;

    float ax1[RPT], ay1[RPT], ax2[RPT], ay2[RPT], aa[RPT], bn[RPT], bs[RPT];
    int bj[RPT];
#pragma unroll
    for (int r = 0; r < RPT; r++) {
        int i = base + r * TB;
        int ii = (i < NTOT) ? i : 0;
        if (ii < N_ROIS) {
            const float* p = rois + (size_t)ii * 5;
            ax1[r] = p[1]; ay1[r] = p[2]; ax2[r] = p[3]; ay2[r] = p[4];
        } else {
            const float* p = gtb + (size_t)(ii - N_ROIS) * 4;
            ax1[r] = p[0]; ay1[r] = p[1]; ax2[r] = p[2]; ay2[r] = p[3];
        }
        aa[r] = __fmul_rn(ax2[r] - ax1[r] + 1.0f, ay2[r] - ay1[r] + 1.0f);
        bn[r] = 0.0f; bs[r] = 1.0f; bj[r] = 0;
    }

#pragma unroll 4
    for (int j = 0; j < G; j++) {
        float4 b = sb[j];
        float  ab = sa[j];
#pragma unroll
        for (int r = 0; r < RPT; r++) {
            float xx1 = fmaxf(ax1[r], b.x);
            float yy1 = fmaxf(ay1[r], b.y);
            float xx2 = fminf(ax2[r], b.z);
            float yy2 = fminf(ay2[r], b.w);
            float iw = fmaxf(xx2 - xx1 + 1.0f, 0.0f);
            float ih = fmaxf(yy2 - yy1 + 1.0f, 0.0f);
            float inter = __fmul_rn(iw, ih);
            float S = aa[r] + ab;   // area_a + area_b (same rounding as reference)
            // iou ordering: inter/(S-inter) ordering == inter/S ordering (exact, S>0)
            if (__fmul_rn(inter, bs[r]) > __fmul_rn(bn[r], S)) {
                bn[r] = inter; bs[r] = S; bj[r] = j;
            }
        }
    }

#pragma unroll
    for (int r = 0; r < RPT; r++) {
        int i = base + r * TB;
        if (i >= NTOT) continue;
        // max overlap with reference rounding: denom = (area_a+area_b) - inter
        float mov = __fdiv_rn(bn[r], bs[r] - bn[r]);
        bool fg = (mov >= 0.5f);
        bool bg = (mov < 0.5f) && (mov >= 0.1f);
        if (fg || bg) {
            uint2 y = threefry42(0u, (unsigned)i);
            unsigned m = ((y.x ^ y.y) >> 9) + 1u;   // 1 .. 2^23, monotone in u
            unsigned long long rec =
                ((unsigned long long)m << 25) |
                ((unsigned long long)(0x3FFFFu - (unsigned)i) << 7) |
                (unsigned long long)(unsigned)bj[r];
            int sel = fg ? 0 : 1;
            unsigned bb = (m - 1u) >> 11;                 // 0..4095
            unsigned p = atomicAdd(&g_bcnt[sel][bb], 1u);
            if (p < CAP) g_bucket[sel][bb * CAP + p] = rec;
        }
    }
}

// ---------------- K2: radix select + bitonic sort top-128 per selector ----------------
__global__ void __launch_bounds__(512) k_select() {
    __shared__ unsigned           schunk[512];
    __shared__ unsigned long long skey[512];
    __shared__ int                sB;
    int sel = blockIdx.x;
    int t = threadIdx.x;

    unsigned loc[8];
    unsigned csum = 0;
#pragma unroll
    for (int k = 0; k < 8; k++) { loc[k] = g_bcnt[sel][t * 8 + k]; csum += loc[k]; }
    schunk[t] = csum;
    if (t == 0) sB = 0;
    __syncthreads();

    // suffix scan (inclusive from top) over 512 chunk sums
    for (int off = 1; off < 512; off <<= 1) {
        unsigned v = schunk[t];
        unsigned add = (t + off < 512) ? schunk[t + off] : 0u;
        __syncthreads();
        schunk[t] = v + add;
        __syncthreads();
    }
    unsigned ex = schunk[t] - csum;   // sum over chunks strictly above mine

    // per-bin inclusive-from-top cumulative C
    unsigned Carr[8];
    {
        unsigned suf = 0;
#pragma unroll
        for (int k = 7; k >= 0; k--) { suf += loc[k]; Carr[k] = ex + suf; }
    }
#pragma unroll
    for (int k = 0; k < 8; k++)
        if (Carr[k] >= 128u) atomicMax(&sB, t * 8 + k);
    skey[t] = 0ull;
    __syncthreads();
    int B = sB;   // highest bin whose inclusive-from-top count reaches 128

    // gather entries from bins >= B into compact shared array (expected ~190)
#pragma unroll
    for (int k = 0; k < 8; k++) {
        int bin = t * 8 + k;
        if (bin >= B && loc[k] > 0) {
            unsigned cnt = loc[k] < CAP ? loc[k] : CAP;
            unsigned off = Carr[k] - loc[k];   // entries in bins above this one
            for (unsigned e = 0; e < cnt; e++) {
                unsigned pos = off + e;
                if (pos < 512) skey[pos] = g_bucket[sel][bin * CAP + e];
            }
        }
    }
    __syncthreads();

    // bitonic sort 512 u64 ascending (1 element per thread)
    for (unsigned k = 2; k <= 512; k <<= 1) {
        for (unsigned j = k >> 1; j > 0; j >>= 1) {
            unsigned ixj = (unsigned)t ^ j;
            if (ixj > (unsigned)t) {
                bool up = ((t & k) == 0);
                unsigned long long a = skey[t], b = skey[ixj];
                if (up ? (a > b) : (a < b)) { skey[t] = b; skey[ixj] = a; }
            }
            __syncthreads();
        }
    }
    // top-128 descending by (key, then smaller original index first)
    if (t < 128) g_keep64[sel * 128 + t] = skey[511 - t];
}

// ---------------- K3: per-row gather: rois, labels, 4 regression targets ----------------
__global__ void __launch_bounds__(256) k_rows(const float* __restrict__ rois,
                                              const float* __restrict__ gtb,
                                              const int* __restrict__ gtl,
                                              float* __restrict__ out) {
    int r = threadIdx.x;  // 0..255
    unsigned long long rec = g_keep64[r];
    unsigned idx = 0x3FFFFu - (unsigned)((rec >> 7) & 0x3FFFFu);
    int ga = (int)(rec & 0x7Fu);
    if (idx >= NTOT) { idx = 0; ga = 0; }

    float c0, x1, y1, x2, y2;
    if (idx < N_ROIS) {
        const float* p = rois + (size_t)idx * 5;
        c0 = p[0]; x1 = p[1]; y1 = p[2]; x2 = p[3]; y2 = p[4];
    } else {
        const float* p = gtb + (size_t)(idx - N_ROIS) * 4;
        c0 = 0.0f; x1 = p[0]; y1 = p[1]; x2 = p[2]; y2 = p[3];
    }

    // fg half: valid_fg is always true (>=128 fg guaranteed by gt self-match)
    int label = (r < 128) ? gtl[ga] : 0;
    g_label[r] = label;

    // rois [256,5] at offset 0
    out[r * 5 + 0] = c0;
    out[r * 5 + 1] = x1;
    out[r * 5 + 2] = y1;
    out[r * 5 + 3] = x2;
    out[r * 5 + 4] = y2;
    // labels [256] at offset 1280
    out[1280 + r] = (float)label;

    const float* g = gtb + (size_t)ga * 4;
    float ew = x2 - x1 + 1.0f, eh = y2 - y1 + 1.0f;
    float ecx = x1 + 0.5f * ew, ecy = y1 + 0.5f * eh;
    float gw = g[2] - g[0] + 1.0f, gh = g[3] - g[1] + 1.0f;
    float gcx = g[0] + 0.5f * gw, gcy = g[1] + 0.5f * gh;
    g_tgt[r][0] = (gcx - ecx) / ew;
    g_tgt[r][1] = (gcy - ecy) / eh;
    g_tgt[r][2] = logf(gw / ew);
    g_tgt[r][3] = logf(gh / eh);
}

// ---------------- K4: parallel bbox_targets fill + counter re-zero ----------------
__global__ void __launch_bounds__(256) k_fill(float* __restrict__ out) {
    int e = blockIdx.x * blockDim.x + threadIdx.x;
    if (e < BBOX_ELEMS) {
        int row = e / 84;
        int col = e - row * 84;
        int lab = g_label[row];
        float v = 0.0f;
        int c0 = lab * 4;
        if (lab > 0 && col >= c0 && col < c0 + 4)
            v = g_tgt[row][col - c0];
        out[1536 + e] = v;
    } else {
        int z = e - BBOX_ELEMS;
        if (z < CNT_WORDS) ((unsigned*)g_bcnt)[z] = 0u;   // clean for next replay
    }
}

// ---------------- launch ----------------
extern "C" void kernel_launch(void* const* d_in, const int* in_sizes, int n_in,
                              void* d_out, int out_size) {
    const float* all_rois = nullptr;  // 1,250,000 elems
    const float* gtb      = nullptr;  // 512 elems
    const int*   gtl      = nullptr;  // 128 elems
    for (int k = 0; k < n_in; k++) {
        if (in_sizes[k] == N_ROIS * 5) all_rois = (const float*)d_in[k];
        else if (in_sizes[k] == G * 4) gtb = (const float*)d_in[k];
        else if (in_sizes[k] == G)     gtl = (const int*)d_in[k];
    }
    float* out = (float*)d_out;

    k_iou<<<(NTOT + TB * RPT - 1) / (TB * RPT), TB>>>(all_rois, gtb);
    k_select<<<2, 512>>>();
    k_rows<<<1, 256>>>(all_rois, gtb, gtl, out);
    k_fill<<<(BBOX_ELEMS + CNT_WORDS + 255) / 256, 256>>>(out);
}